// round 15
// baseline (speedup 1.0000x reference)
#include <cuda_runtime.h>
#include <cuda_fp16.h>
#include <stdint.h>

// Problem constants
#define C_CH   256
#define S_LEN  512
#define D_DIM  256
#define D_IN   256
#define D_FF   1024
#define NROWS  (C_CH * S_LEN)              // 131072
#define ELEMS  ((long long)NROWS * D_DIM)  // 33,554,432

// ---------------------------------------------------------------------------
// Scratch (static; no allocation allowed)
// ---------------------------------------------------------------------------
__device__ float  g_x   [NROWS * D_DIM];                 // fp32 residual
__device__ __half g_in_h[NROWS * D_IN];                  // input fp16
__device__ __half g_n_h [NROWS * D_DIM];                 // layernorm out
__device__ __half g_nT_h[NROWS * D_DIM];                 // n transposed per channel
__device__ __half g_o_h [NROWS * D_DIM];                 // attention out
__device__ __half g_ffn_h[(size_t)NROWS * D_FF];         // FFN hidden
__device__ __half g_attn_h[(size_t)C_CH * S_LEN * S_LEN];// probs fp16
__device__ __half g_wembt[D_DIM * D_IN];                 // W_emb^T [256,256]
__device__ __half g_w1t [D_FF * D_DIM];                  // W1^T [1024,256]
__device__ __half g_w2t [D_DIM * D_FF];                  // W2^T [256,1024]
__device__ float  g_y   [C_CH];
__device__ float  g_gate[C_CH];

__device__ __forceinline__ uint32_t f2h2(float a, float b) {
    __half2 h = __floats2half2_rn(a, b);
    return *(uint32_t*)&h;
}

// cp.async helpers (L2-only path)
#define CP16(dst, src) asm volatile("cp.async.cg.shared.global [%0], [%1], 16;\n" :: "r"(dst), "l"(src))
#define CP_COMMIT()    asm volatile("cp.async.commit_group;\n")
#define CP_WAIT0()     asm volatile("cp.async.wait_group 0;\n")
#define CP_WAIT1()     asm volatile("cp.async.wait_group 1;\n")

__device__ __forceinline__ void ldsmx4(uint32_t& r0, uint32_t& r1,
                                       uint32_t& r2, uint32_t& r3, uint32_t a) {
    asm volatile("ldmatrix.sync.aligned.m8n8.x4.shared.b16 {%0,%1,%2,%3}, [%4];"
                 : "=r"(r0), "=r"(r1), "=r"(r2), "=r"(r3) : "r"(a));
}
__device__ __forceinline__ void ldsmx2(uint32_t& r0, uint32_t& r1, uint32_t a) {
    asm volatile("ldmatrix.sync.aligned.m8n8.x2.shared.b16 {%0,%1}, [%2];"
                 : "=r"(r0), "=r"(r1) : "r"(a));
}

// ===========================================================================
// Unified NT fp16 GEMM:  C = alpha * A @ B^T [+bias] [relu]
//   A: [M,K] half row-major,  B: [N,K] half row-major, batch via blockIdx.z.
//   Tile 128x128x32, 256 threads (8 warps 2x4), warp tile 64x32.
//   3-stage cp.async ring (dynamic smem, 61440B), wait_group 1 steady-state.
//   Stage layout: A 128 rows x 20 u32 (80B stride) at +0, B same at +10240B.
//   80B stride is conflict-free for cp.async stores and ldmatrix reads (R12-proven).
// ===========================================================================
#define STAGE_BYTES 20480
#define B_OFF_BYTES 10240

template<bool OUT_HALF, bool RELU, bool HAS_BIAS>
__global__ __launch_bounds__(256)
void mma_nt(const __half* __restrict__ Aall, const __half* __restrict__ Ball,
            const float* __restrict__ bias, void* __restrict__ Call,
            int M, int N, int K, float alpha,
            long long sA, long long sB, long long sC)
{
    extern __shared__ uint32_t smem_dyn[];
    const uint32_t smemBase = (uint32_t)__cvta_generic_to_shared(smem_dyn);

    const __half* A = Aall + (long long)blockIdx.z * sA;
    const __half* B = Ball + (long long)blockIdx.z * sB;

    const int t     = threadIdx.x;
    const int lane  = t & 31;
    const int warp  = t >> 5;
    const int warpM = warp >> 2;   // 0..1
    const int warpN = warp & 3;    // 0..3
    const int g8    = lane >> 2;   // 0..7
    const int tig   = lane & 3;    // 0..3

    // global loader: thread t -> row t>>1, 32B chunk (t&1)
    const int lRow = t >> 1;
    const __half* aSrc = A + (size_t)((blockIdx.y << 7) + lRow) * K + ((t & 1) << 4);
    const __half* bSrc = B + (size_t)((blockIdx.x << 7) + lRow) * K + ((t & 1) << 4);

    // per-thread smem store byte offsets within a stage
    const uint32_t stOffA = (uint32_t)(lRow * 80 + ((t & 1) << 5));
    const uint32_t stOffB = stOffA + B_OFF_BYTES;

    // ldmatrix lane byte offsets within a stage
    const uint32_t aLdOff = (uint32_t)(((warpM << 6) + (lane & 15)) * 80 + ((lane >> 4) << 4));
    const uint32_t bLdOff = (uint32_t)(B_OFF_BYTES + ((warpN << 5) + (lane & 7)) * 80
                                       + (((lane >> 3) & 1) << 4));

    float acc[4][4][4];
    #pragma unroll
    for (int i = 0; i < 4; i++)
        #pragma unroll
        for (int j = 0; j < 4; j++)
            #pragma unroll
            for (int r = 0; r < 4; r++) acc[i][j][r] = 0.0f;

    const int nslabs = K >> 5;

    auto issue = [&](int slab, int stage) {
        const uint32_t base = smemBase + (uint32_t)stage * STAGE_BYTES;
        const __half* as = aSrc + (slab << 5);
        const __half* bs = bSrc + (slab << 5);
        CP16(base + stOffA,      as);
        CP16(base + stOffA + 16, as + 8);
        CP16(base + stOffB,      bs);
        CP16(base + stOffB + 16, bs + 8);
        CP_COMMIT();
    };

    // prologue: 2 slabs in flight
    issue(0, 0);
    if (nslabs > 1) issue(1, 1);

    int stage = 0;
    for (int i = 0; i < nslabs; i++) {
        if (i + 1 < nslabs) CP_WAIT1(); else CP_WAIT0();
        __syncthreads();

        if (i + 2 < nslabs) {
            int ns = stage + 2; if (ns >= 3) ns -= 3;
            issue(i + 2, ns);
        }

        const uint32_t aLd = smemBase + (uint32_t)stage * STAGE_BYTES + aLdOff;
        const uint32_t bLd = smemBase + (uint32_t)stage * STAGE_BYTES + bLdOff;

        #pragma unroll
        for (int ks = 0; ks < 2; ks++) {
            uint32_t af[4][4], bf[4][2];
            #pragma unroll
            for (int mt = 0; mt < 4; mt++)
                ldsmx4(af[mt][0], af[mt][1], af[mt][2], af[mt][3],
                       aLd + mt * (16 * 80) + ks * 32);
            #pragma unroll
            for (int nt = 0; nt < 4; nt++)
                ldsmx2(bf[nt][0], bf[nt][1],
                       bLd + nt * (8 * 80) + ks * 32);
            #pragma unroll
            for (int mt = 0; mt < 4; mt++)
                #pragma unroll
                for (int nt = 0; nt < 4; nt++)
                    asm volatile(
                        "mma.sync.aligned.m16n8k16.row.col.f32.f16.f16.f32 "
                        "{%0,%1,%2,%3}, {%4,%5,%6,%7}, {%8,%9}, {%0,%1,%2,%3};"
                        : "+f"(acc[mt][nt][0]), "+f"(acc[mt][nt][1]),
                          "+f"(acc[mt][nt][2]), "+f"(acc[mt][nt][3])
                        : "r"(af[mt][0]), "r"(af[mt][1]),
                          "r"(af[mt][2]), "r"(af[mt][3]),
                          "r"(bf[nt][0]), "r"(bf[nt][1]));
        }
        if (++stage == 3) stage = 0;
    }

    // ---- epilogue ----
    const int rowB = (blockIdx.y << 7) + (warpM << 6) + g8;
    const int colB = (blockIdx.x << 7) + (warpN << 5) + (tig << 1);

    #pragma unroll
    for (int nt = 0; nt < 4; nt++) {
        const int col = colB + (nt << 3);
        float b0 = 0.f, b1 = 0.f;
        if (HAS_BIAS) { b0 = bias[col]; b1 = bias[col + 1]; }
        #pragma unroll
        for (int mt = 0; mt < 4; mt++) {
            float v0 = acc[mt][nt][0] * alpha + b0;
            float v1 = acc[mt][nt][1] * alpha + b1;
            float v2 = acc[mt][nt][2] * alpha + b0;
            float v3 = acc[mt][nt][3] * alpha + b1;
            if (RELU) {
                v0 = fmaxf(v0, 0.f); v1 = fmaxf(v1, 0.f);
                v2 = fmaxf(v2, 0.f); v3 = fmaxf(v3, 0.f);
            }
            const int r0 = rowB + (mt << 4);
            if (OUT_HALF) {
                __half* Cp = (__half*)Call + (long long)blockIdx.z * sC;
                *(__half2*)(Cp + (size_t)r0 * N + col)       = __floats2half2_rn(v0, v1);
                *(__half2*)(Cp + (size_t)(r0 + 8) * N + col) = __floats2half2_rn(v2, v3);
            } else {
                float* Cp = (float*)Call + (long long)blockIdx.z * sC;
                *(float2*)(Cp + (size_t)r0 * N + col)       = make_float2(v0, v1);
                *(float2*)(Cp + (size_t)(r0 + 8) * N + col) = make_float2(v2, v3);
            }
        }
    }
}

// ---------------------------------------------------------------------------
// fp32 -> fp16 convert (8 elems/thread)
// ---------------------------------------------------------------------------
__global__ __launch_bounds__(256)
void f2h_kernel(const float* __restrict__ in, __half* __restrict__ out)
{
    const long long i = ((long long)blockIdx.x * 256 + threadIdx.x) << 3;
    const float4 v0 = *(const float4*)(in + i);
    const float4 v1 = *(const float4*)(in + i + 4);
    uint4 o;
    o.x = f2h2(v0.x, v0.y);
    o.y = f2h2(v0.z, v0.w);
    o.z = f2h2(v1.x, v1.y);
    o.w = f2h2(v1.z, v1.w);
    *(uint4*)(out + i) = o;
}

// ---------------------------------------------------------------------------
// Transposes
// ---------------------------------------------------------------------------
__global__ __launch_bounds__(256)
void transpose_h(const __half* __restrict__ in, __half* __restrict__ out,
                 int R, int C)
{
    __shared__ __half tile[32][33];
    const size_t base = (size_t)blockIdx.z * R * C;
    const int x0 = blockIdx.x << 5, y0 = blockIdx.y << 5;
    const int tx = threadIdx.x & 31, ty = threadIdx.x >> 5;
    #pragma unroll
    for (int j = 0; j < 4; j++) {
        const int r = y0 + ty + (j << 3);
        tile[ty + (j << 3)][tx] = in[base + (size_t)r * C + x0 + tx];
    }
    __syncthreads();
    #pragma unroll
    for (int j = 0; j < 4; j++) {
        const int c = x0 + ty + (j << 3);
        out[base + (size_t)c * R + y0 + tx] = tile[tx][ty + (j << 3)];
    }
}

__global__ __launch_bounds__(256)
void transpose_f2h(const float* __restrict__ in, __half* __restrict__ out,
                   int R, int C)
{
    __shared__ float tile[32][33];
    const int x0 = blockIdx.x << 5, y0 = blockIdx.y << 5;
    const int tx = threadIdx.x & 31, ty = threadIdx.x >> 5;
    #pragma unroll
    for (int j = 0; j < 4; j++) {
        const int r = y0 + ty + (j << 3);
        tile[ty + (j << 3)][tx] = in[(size_t)r * C + x0 + tx];
    }
    __syncthreads();
    #pragma unroll
    for (int j = 0; j < 4; j++) {
        const int c = x0 + ty + (j << 3);
        out[(size_t)c * R + y0 + tx] = __float2half_rn(tile[tx][ty + (j << 3)]);
    }
}

// ---------------------------------------------------------------------------
// Reductions / elementwise
// ---------------------------------------------------------------------------
__inline__ __device__ float warpSum(float v) {
    #pragma unroll
    for (int o = 16; o > 0; o >>= 1) v += __shfl_xor_sync(0xffffffffu, v, o);
    return v;
}
__inline__ __device__ float warpMax(float v) {
    #pragma unroll
    for (int o = 16; o > 0; o >>= 1) v = fmaxf(v, __shfl_xor_sync(0xffffffffu, v, o));
    return v;
}

// LayerNorm over D=256: one WARP per row
__global__ __launch_bounds__(256)
void ln_kernel(const float* __restrict__ x, const float* __restrict__ gamma,
               const float* __restrict__ beta, __half* __restrict__ out)
{
    const int warp = threadIdx.x >> 5, lane = threadIdx.x & 31;
    const long long row = (long long)blockIdx.x * 8 + warp;
    const float* xr = x + row * D_DIM + (lane << 3);

    const float4 v0 = *(const float4*)(xr);
    const float4 v1 = *(const float4*)(xr + 4);

    float s  = (v0.x + v0.y) + (v0.z + v0.w) + (v1.x + v1.y) + (v1.z + v1.w);
    float sq = v0.x*v0.x + v0.y*v0.y + v0.z*v0.z + v0.w*v0.w
             + v1.x*v1.x + v1.y*v1.y + v1.z*v1.z + v1.w*v1.w;
    s  = warpSum(s);
    sq = warpSum(sq);

    const float mu  = s * (1.0f / D_DIM);
    const float var = sq * (1.0f / D_DIM) - mu * mu;
    const float rs  = rsqrtf(var + 1e-5f);

    const float4 g0 = *(const float4*)(gamma + (lane << 3));
    const float4 g1 = *(const float4*)(gamma + (lane << 3) + 4);
    const float4 b0 = *(const float4*)(beta  + (lane << 3));
    const float4 b1 = *(const float4*)(beta  + (lane << 3) + 4);

    uint4 o;
    o.x = f2h2((v0.x - mu) * rs * g0.x + b0.x, (v0.y - mu) * rs * g0.y + b0.y);
    o.y = f2h2((v0.z - mu) * rs * g0.z + b0.z, (v0.w - mu) * rs * g0.w + b0.w);
    o.z = f2h2((v1.x - mu) * rs * g1.x + b1.x, (v1.y - mu) * rs * g1.y + b1.y);
    o.w = f2h2((v1.z - mu) * rs * g1.z + b1.z, (v1.w - mu) * rs * g1.w + b1.w);
    *(uint4*)(out + row * D_DIM + (lane << 3)) = o;
}

// Softmax over S=512 in-place (fp32) + fp16 copy
__global__ __launch_bounds__(128)
void softmax_kernel(float* __restrict__ p, __half* __restrict__ ph_all)
{
    const long long row = blockIdx.x;
    float* pr = p + row * S_LEN;
    __half* ph = ph_all + row * S_LEN;
    const int t = threadIdx.x;
    const int w = t >> 5, l = t & 31;

    float4 a = *(float4*)(pr + (t << 2));
    __shared__ float sh[4], sh2[4];

    float m = fmaxf(fmaxf(a.x, a.y), fmaxf(a.z, a.w));
    m = warpMax(m);
    if (l == 0) sh[w] = m;
    __syncthreads();
    m = fmaxf(fmaxf(sh[0], sh[1]), fmaxf(sh[2], sh[3]));

    a.x = __expf(a.x - m); a.y = __expf(a.y - m);
    a.z = __expf(a.z - m); a.w = __expf(a.w - m);
    float s = warpSum(a.x + a.y + a.z + a.w);
    if (l == 0) sh2[w] = s;
    __syncthreads();
    const float inv = 1.0f / (sh2[0] + sh2[1] + sh2[2] + sh2[3]);

    a.x *= inv; a.y *= inv; a.z *= inv; a.w *= inv;
    *(float4*)(pr + (t << 2)) = a;
    *(__half2*)(ph + (t << 2))     = __floats2half2_rn(a.x, a.y);
    *(__half2*)(ph + (t << 2) + 2) = __floats2half2_rn(a.z, a.w);
}

// Per-channel mean
__global__ __launch_bounds__(256)
void chmean_kernel(const float* __restrict__ h, float* __restrict__ y)
{
    const int c = blockIdx.x;
    const float4* hc = (const float4*)(h + (long long)c * S_LEN * D_DIM);
    float s = 0.f;
    for (int i = threadIdx.x; i < S_LEN * D_DIM / 4; i += 256) {
        float4 v = hc[i];
        s += (v.x + v.y) + (v.z + v.w);
    }
    __shared__ float sh[8];
    const int w = threadIdx.x >> 5, l = threadIdx.x & 31;
    s = warpSum(s);
    if (l == 0) sh[w] = s;
    __syncthreads();
    if (w == 0) {
        float v = (l < 8) ? sh[l] : 0.f;
        v = warpSum(v);
        if (l == 0) y[c] = v * (1.0f / (S_LEN * D_DIM));
    }
}

// SE gate
__global__ __launch_bounds__(256)
void se_kernel(const float* __restrict__ y,
               const float* __restrict__ W1, const float* __restrict__ b1,
               const float* __restrict__ W2, const float* __restrict__ b2,
               float* __restrict__ gate)
{
    __shared__ float ys[C_CH];
    __shared__ float hid[16];
    const int t = threadIdx.x;
    ys[t] = y[t];
    __syncthreads();
    if (t < 16) {
        float s = b1[t];
        #pragma unroll 8
        for (int c = 0; c < C_CH; c++) s += ys[c] * W1[c * 16 + t];
        hid[t] = fmaxf(s, 0.f);
    }
    __syncthreads();
    float s = b2[t];
    #pragma unroll
    for (int j = 0; j < 16; j++) s += hid[j] * W2[j * C_CH + t];
    gate[t] = 1.0f / (1.0f + __expf(-s));
}

// out = h * gate[c] + x
__global__ __launch_bounds__(256)
void final_kernel(float* __restrict__ out, const float* __restrict__ x,
                  const float* __restrict__ gate)
{
    const long long i4 = (long long)blockIdx.x * 256 + threadIdx.x;
    const int c = (int)(i4 >> 15);
    const float g = gate[c];
    float4 h = ((float4*)out)[i4];
    float4 xv = ((const float4*)x)[i4];
    h.x = h.x * g + xv.x;
    h.y = h.y * g + xv.y;
    h.z = h.z * g + xv.z;
    h.w = h.w * g + xv.w;
    ((float4*)out)[i4] = h;
}

// ---------------------------------------------------------------------------
// Launch
// ---------------------------------------------------------------------------
extern "C" void kernel_launch(void* const* d_in, const int* in_sizes, int n_in,
                              void* d_out, int out_size)
{
    const float* input = (const float*)d_in[0];
    const float* W_emb = (const float*)d_in[1];
    const float* b_emb = (const float*)d_in[2];
    const float* ln_g  = (const float*)d_in[3];
    const float* ln_b  = (const float*)d_in[4];
    const float* W1    = (const float*)d_in[5];
    const float* b1    = (const float*)d_in[6];
    const float* W2    = (const float*)d_in[7];
    const float* b2    = (const float*)d_in[8];
    const float* seW1  = (const float*)d_in[9];
    const float* seb1  = (const float*)d_in[10];
    const float* seW2  = (const float*)d_in[11];
    const float* seb2  = (const float*)d_in[12];

    float* out  = (float*)d_out;               // [C,S,D]
    float* attn = out + ELEMS;                 // [C,S,S] fp32 (output 1)

    float  *px, *py, *pg;
    __half *pih, *pn, *pnT, *po, *pffn, *pah, *pwet, *pw1t, *pw2t;
    cudaGetSymbolAddress((void**)&px,   g_x);
    cudaGetSymbolAddress((void**)&pih,  g_in_h);
    cudaGetSymbolAddress((void**)&pn,   g_n_h);
    cudaGetSymbolAddress((void**)&pnT,  g_nT_h);
    cudaGetSymbolAddress((void**)&po,   g_o_h);
    cudaGetSymbolAddress((void**)&pffn, g_ffn_h);
    cudaGetSymbolAddress((void**)&pah,  g_attn_h);
    cudaGetSymbolAddress((void**)&pwet, g_wembt);
    cudaGetSymbolAddress((void**)&pw1t, g_w1t);
    cudaGetSymbolAddress((void**)&pw2t, g_w2t);
    cudaGetSymbolAddress((void**)&py,   g_y);
    cudaGetSymbolAddress((void**)&pg,   g_gate);

    // raise dynamic smem limit for the GEMM instantiations (idempotent)
    const int DYN = 3 * STAGE_BYTES;   // 61440
    cudaFuncSetAttribute(mma_nt<false, false, false>, cudaFuncAttributeMaxDynamicSharedMemorySize, DYN);
    cudaFuncSetAttribute(mma_nt<true,  false, false>, cudaFuncAttributeMaxDynamicSharedMemorySize, DYN);
    cudaFuncSetAttribute(mma_nt<true,  true,  true >, cudaFuncAttributeMaxDynamicSharedMemorySize, DYN);
    cudaFuncSetAttribute(mma_nt<false, false, true >, cudaFuncAttributeMaxDynamicSharedMemorySize, DYN);

    const dim3 blk(256);
    const long long strideN = (long long)S_LEN * D_DIM;   // 131072
    const long long strideP = (long long)S_LEN * S_LEN;   // 262144

    // 0) weight transposes (fp32 -> fp16, transposed) + input convert
    transpose_f2h<<<dim3(D_DIM / 32, D_IN / 32), blk>>>(W_emb, pwet, D_IN, D_DIM);
    transpose_f2h<<<dim3(D_FF / 32, D_DIM / 32), blk>>>(W1, pw1t, D_DIM, D_FF);
    transpose_f2h<<<dim3(D_DIM / 32, D_FF / 32), blk>>>(W2, pw2t, D_FF, D_DIM);
    f2h_kernel<<<(unsigned)(ELEMS / 2048), blk>>>(input, pih);

    // 1) x = input @ W_emb + b_emb  (NT, B = W_emb^T) -> fp32
    mma_nt<false, false, true><<<dim3(D_DIM / 128, NROWS / 128, 1), blk, DYN>>>(
        pih, pwet, b_emb, px, NROWS, D_DIM, D_IN, 1.0f, 0, 0, 0);

    // 2) n = LayerNorm(x) -> fp16
    ln_kernel<<<NROWS / 8, 256>>>(px, ln_g, ln_b, pn);

    // 3) nT per channel
    transpose_h<<<dim3(D_DIM / 32, S_LEN / 32, C_CH), blk>>>(pn, pnT, S_LEN, D_DIM);

    // 4) scores = (n @ n^T)/16 per channel -> attn fp32
    mma_nt<false, false, false><<<dim3(S_LEN / 128, S_LEN / 128, C_CH), blk, DYN>>>(
        pn, pn, nullptr, attn, S_LEN, S_LEN, D_DIM, 0.0625f,
        strideN, strideN, strideP);

    // 5) softmax in-place + fp16 copy
    softmax_kernel<<<C_CH * S_LEN, 128>>>(attn, pah);

    // 6) o = attn @ n per channel (NT with B = nT) -> fp16
    mma_nt<true, false, false><<<dim3(D_DIM / 128, S_LEN / 128, C_CH), blk, DYN>>>(
        pah, pnT, nullptr, po, S_LEN, D_DIM, S_LEN, 1.0f,
        strideP, strideN, strideN);

    // 7) h1 = relu(o @ W1 + b1) (NT with B = W1T) -> fp16
    mma_nt<true, true, true><<<dim3(D_FF / 128, NROWS / 128, 1), blk, DYN>>>(
        po, pw1t, b1, pffn, NROWS, D_FF, D_DIM, 1.0f, 0, 0, 0);

    // 8) h = h1 @ W2 + b2 (NT with B = W2T) -> fp32 out region
    mma_nt<false, false, true><<<dim3(D_DIM / 128, NROWS / 128, 1), blk, DYN>>>(
        pffn, pw2t, b2, out, NROWS, D_DIM, D_FF, 1.0f, 0, 0, 0);

    // 9) y[c] = mean(h[c])
    chmean_kernel<<<C_CH, 256>>>(out, py);

    // 10) SE gate
    se_kernel<<<1, 256>>>(py, seW1, seb1, seW2, seb2, pg);

    // 11) out = h * g[c] + x
    final_kernel<<<(unsigned)(ELEMS / 1024), 256>>>(out, px, pg);
}

// round 16
// speedup vs baseline: 1.0025x; 1.0025x over previous
#include <cuda_runtime.h>
#include <cuda_fp16.h>
#include <stdint.h>

// Problem constants
#define C_CH   256
#define S_LEN  512
#define D_DIM  256
#define D_IN   256
#define D_FF   1024
#define NROWS  (C_CH * S_LEN)              // 131072
#define ELEMS  ((long long)NROWS * D_DIM)  // 33,554,432

// ---------------------------------------------------------------------------
// Scratch (static; no allocation allowed)
// ---------------------------------------------------------------------------
__device__ float  g_x   [NROWS * D_DIM];                 // fp32 residual
__device__ __half g_in_h[NROWS * D_IN];                  // input fp16
__device__ __half g_n_h [NROWS * D_DIM];                 // layernorm out
__device__ __half g_nT_h[NROWS * D_DIM];                 // n transposed per channel
__device__ __half g_o_h [NROWS * D_DIM];                 // attention out
__device__ __half g_ffn_h[(size_t)NROWS * D_FF];         // FFN hidden
__device__ __half g_attn_h[(size_t)C_CH * S_LEN * S_LEN];// probs fp16
__device__ __half g_wembt[D_DIM * D_IN];                 // W_emb^T [256,256]
__device__ __half g_w1t [D_FF * D_DIM];                  // W1^T [1024,256]
__device__ __half g_w2t [D_DIM * D_FF];                  // W2^T [256,1024]
__device__ float  g_y   [C_CH];
__device__ float  g_gate[C_CH];

__device__ __forceinline__ uint32_t f2h2(float a, float b) {
    __half2 h = __floats2half2_rn(a, b);
    return *(uint32_t*)&h;
}

// cp.async helpers (L2-only path)
#define CP16(dst, src) asm volatile("cp.async.cg.shared.global [%0], [%1], 16;\n" :: "r"(dst), "l"(src))
#define CP_COMMIT()    asm volatile("cp.async.commit_group;\n")
#define CP_WAIT0()     asm volatile("cp.async.wait_group 0;\n")
#define CP_WAIT1()     asm volatile("cp.async.wait_group 1;\n")

__device__ __forceinline__ void ldsmx4(uint32_t& r0, uint32_t& r1,
                                       uint32_t& r2, uint32_t& r3, uint32_t a) {
    asm volatile("ldmatrix.sync.aligned.m8n8.x4.shared.b16 {%0,%1,%2,%3}, [%4];"
                 : "=r"(r0), "=r"(r1), "=r"(r2), "=r"(r3) : "r"(a));
}
__device__ __forceinline__ void ldsmx2(uint32_t& r0, uint32_t& r1, uint32_t a) {
    asm volatile("ldmatrix.sync.aligned.m8n8.x2.shared.b16 {%0,%1}, [%2];"
                 : "=r"(r0), "=r"(r1) : "r"(a));
}

// ===========================================================================
// Unified NT fp16 GEMM:  C = alpha * A @ B^T [+bias] [relu]
//   A: [M,K] half row-major,  B: [N,K] half row-major, batch via blockIdx.z.
//   Tile 128x128x32, 256 threads (8 warps 2x4), warp tile 64x32.
//   3-stage cp.async ring (dynamic smem, 61440B), wait_group 1 steady-state.
//   Stage layout: A 128 rows x 20 u32 (80B stride) at +0, B same at +10240B.
//   80B stride is conflict-free for cp.async stores and ldmatrix reads (R12-proven).
// ===========================================================================
#define STAGE_BYTES 20480
#define B_OFF_BYTES 10240

template<bool OUT_HALF, bool RELU, bool HAS_BIAS>
__global__ __launch_bounds__(256)
void mma_nt(const __half* __restrict__ Aall, const __half* __restrict__ Ball,
            const float* __restrict__ bias, void* __restrict__ Call,
            int M, int N, int K, float alpha,
            long long sA, long long sB, long long sC)
{
    extern __shared__ uint32_t smem_dyn[];
    const uint32_t smemBase = (uint32_t)__cvta_generic_to_shared(smem_dyn);

    const __half* A = Aall + (long long)blockIdx.z * sA;
    const __half* B = Ball + (long long)blockIdx.z * sB;

    const int t     = threadIdx.x;
    const int lane  = t & 31;
    const int warp  = t >> 5;
    const int warpM = warp >> 2;   // 0..1
    const int warpN = warp & 3;    // 0..3
    const int g8    = lane >> 2;   // 0..7
    const int tig   = lane & 3;    // 0..3

    // global loader: thread t -> row t>>1, 32B chunk (t&1)
    const int lRow = t >> 1;
    const __half* aSrc = A + (size_t)((blockIdx.y << 7) + lRow) * K + ((t & 1) << 4);
    const __half* bSrc = B + (size_t)((blockIdx.x << 7) + lRow) * K + ((t & 1) << 4);

    // per-thread smem store byte offsets within a stage
    const uint32_t stOffA = (uint32_t)(lRow * 80 + ((t & 1) << 5));
    const uint32_t stOffB = stOffA + B_OFF_BYTES;

    // ldmatrix lane byte offsets within a stage
    const uint32_t aLdOff = (uint32_t)(((warpM << 6) + (lane & 15)) * 80 + ((lane >> 4) << 4));
    const uint32_t bLdOff = (uint32_t)(B_OFF_BYTES + ((warpN << 5) + (lane & 7)) * 80
                                       + (((lane >> 3) & 1) << 4));

    float acc[4][4][4];
    #pragma unroll
    for (int i = 0; i < 4; i++)
        #pragma unroll
        for (int j = 0; j < 4; j++)
            #pragma unroll
            for (int r = 0; r < 4; r++) acc[i][j][r] = 0.0f;

    const int nslabs = K >> 5;

    auto issue = [&](int slab, int stage) {
        const uint32_t base = smemBase + (uint32_t)stage * STAGE_BYTES;
        const __half* as = aSrc + (slab << 5);
        const __half* bs = bSrc + (slab << 5);
        CP16(base + stOffA,      as);
        CP16(base + stOffA + 16, as + 8);
        CP16(base + stOffB,      bs);
        CP16(base + stOffB + 16, bs + 8);
        CP_COMMIT();
    };

    // prologue: 2 slabs in flight
    issue(0, 0);
    if (nslabs > 1) issue(1, 1);

    int stage = 0;
    for (int i = 0; i < nslabs; i++) {
        if (i + 1 < nslabs) CP_WAIT1(); else CP_WAIT0();
        __syncthreads();

        if (i + 2 < nslabs) {
            int ns = stage + 2; if (ns >= 3) ns -= 3;
            issue(i + 2, ns);
        }

        const uint32_t aLd = smemBase + (uint32_t)stage * STAGE_BYTES + aLdOff;
        const uint32_t bLd = smemBase + (uint32_t)stage * STAGE_BYTES + bLdOff;

        #pragma unroll
        for (int ks = 0; ks < 2; ks++) {
            uint32_t af[4][4], bf[4][2];
            #pragma unroll
            for (int mt = 0; mt < 4; mt++)
                ldsmx4(af[mt][0], af[mt][1], af[mt][2], af[mt][3],
                       aLd + mt * (16 * 80) + ks * 32);
            #pragma unroll
            for (int nt = 0; nt < 4; nt++)
                ldsmx2(bf[nt][0], bf[nt][1],
                       bLd + nt * (8 * 80) + ks * 32);
            #pragma unroll
            for (int mt = 0; mt < 4; mt++)
                #pragma unroll
                for (int nt = 0; nt < 4; nt++)
                    asm volatile(
                        "mma.sync.aligned.m16n8k16.row.col.f32.f16.f16.f32 "
                        "{%0,%1,%2,%3}, {%4,%5,%6,%7}, {%8,%9}, {%0,%1,%2,%3};"
                        : "+f"(acc[mt][nt][0]), "+f"(acc[mt][nt][1]),
                          "+f"(acc[mt][nt][2]), "+f"(acc[mt][nt][3])
                        : "r"(af[mt][0]), "r"(af[mt][1]),
                          "r"(af[mt][2]), "r"(af[mt][3]),
                          "r"(bf[nt][0]), "r"(bf[nt][1]));
        }
        if (++stage == 3) stage = 0;
    }

    // ---- epilogue ----
    const int rowB = (blockIdx.y << 7) + (warpM << 6) + g8;
    const int colB = (blockIdx.x << 7) + (warpN << 5) + (tig << 1);

    #pragma unroll
    for (int nt = 0; nt < 4; nt++) {
        const int col = colB + (nt << 3);
        float b0 = 0.f, b1 = 0.f;
        if (HAS_BIAS) { b0 = bias[col]; b1 = bias[col + 1]; }
        #pragma unroll
        for (int mt = 0; mt < 4; mt++) {
            float v0 = acc[mt][nt][0] * alpha + b0;
            float v1 = acc[mt][nt][1] * alpha + b1;
            float v2 = acc[mt][nt][2] * alpha + b0;
            float v3 = acc[mt][nt][3] * alpha + b1;
            if (RELU) {
                v0 = fmaxf(v0, 0.f); v1 = fmaxf(v1, 0.f);
                v2 = fmaxf(v2, 0.f); v3 = fmaxf(v3, 0.f);
            }
            const int r0 = rowB + (mt << 4);
            if (OUT_HALF) {
                __half* Cp = (__half*)Call + (long long)blockIdx.z * sC;
                *(__half2*)(Cp + (size_t)r0 * N + col)       = __floats2half2_rn(v0, v1);
                *(__half2*)(Cp + (size_t)(r0 + 8) * N + col) = __floats2half2_rn(v2, v3);
            } else {
                float* Cp = (float*)Call + (long long)blockIdx.z * sC;
                *(float2*)(Cp + (size_t)r0 * N + col)       = make_float2(v0, v1);
                *(float2*)(Cp + (size_t)(r0 + 8) * N + col) = make_float2(v2, v3);
            }
        }
    }
}

// ---------------------------------------------------------------------------
// fp32 -> fp16 convert (8 elems/thread)
// ---------------------------------------------------------------------------
__global__ __launch_bounds__(256)
void f2h_kernel(const float* __restrict__ in, __half* __restrict__ out)
{
    const long long i = ((long long)blockIdx.x * 256 + threadIdx.x) << 3;
    const float4 v0 = *(const float4*)(in + i);
    const float4 v1 = *(const float4*)(in + i + 4);
    uint4 o;
    o.x = f2h2(v0.x, v0.y);
    o.y = f2h2(v0.z, v0.w);
    o.z = f2h2(v1.x, v1.y);
    o.w = f2h2(v1.z, v1.w);
    *(uint4*)(out + i) = o;
}

// ---------------------------------------------------------------------------
// Transposes
// ---------------------------------------------------------------------------
__global__ __launch_bounds__(256)
void transpose_h(const __half* __restrict__ in, __half* __restrict__ out,
                 int R, int C)
{
    __shared__ __half tile[32][33];
    const size_t base = (size_t)blockIdx.z * R * C;
    const int x0 = blockIdx.x << 5, y0 = blockIdx.y << 5;
    const int tx = threadIdx.x & 31, ty = threadIdx.x >> 5;
    #pragma unroll
    for (int j = 0; j < 4; j++) {
        const int r = y0 + ty + (j << 3);
        tile[ty + (j << 3)][tx] = in[base + (size_t)r * C + x0 + tx];
    }
    __syncthreads();
    #pragma unroll
    for (int j = 0; j < 4; j++) {
        const int c = x0 + ty + (j << 3);
        out[base + (size_t)c * R + y0 + tx] = tile[tx][ty + (j << 3)];
    }
}

__global__ __launch_bounds__(256)
void transpose_f2h(const float* __restrict__ in, __half* __restrict__ out,
                   int R, int C)
{
    __shared__ float tile[32][33];
    const int x0 = blockIdx.x << 5, y0 = blockIdx.y << 5;
    const int tx = threadIdx.x & 31, ty = threadIdx.x >> 5;
    #pragma unroll
    for (int j = 0; j < 4; j++) {
        const int r = y0 + ty + (j << 3);
        tile[ty + (j << 3)][tx] = in[(size_t)r * C + x0 + tx];
    }
    __syncthreads();
    #pragma unroll
    for (int j = 0; j < 4; j++) {
        const int c = x0 + ty + (j << 3);
        out[(size_t)c * R + y0 + tx] = __float2half_rn(tile[tx][ty + (j << 3)]);
    }
}

// ---------------------------------------------------------------------------
// Reductions / elementwise
// ---------------------------------------------------------------------------
__inline__ __device__ float warpSum(float v) {
    #pragma unroll
    for (int o = 16; o > 0; o >>= 1) v += __shfl_xor_sync(0xffffffffu, v, o);
    return v;
}
__inline__ __device__ float warpMax(float v) {
    #pragma unroll
    for (int o = 16; o > 0; o >>= 1) v = fmaxf(v, __shfl_xor_sync(0xffffffffu, v, o));
    return v;
}

// LayerNorm over D=256: one WARP per row
__global__ __launch_bounds__(256)
void ln_kernel(const float* __restrict__ x, const float* __restrict__ gamma,
               const float* __restrict__ beta, __half* __restrict__ out)
{
    const int warp = threadIdx.x >> 5, lane = threadIdx.x & 31;
    const long long row = (long long)blockIdx.x * 8 + warp;
    const float* xr = x + row * D_DIM + (lane << 3);

    const float4 v0 = *(const float4*)(xr);
    const float4 v1 = *(const float4*)(xr + 4);

    float s  = (v0.x + v0.y) + (v0.z + v0.w) + (v1.x + v1.y) + (v1.z + v1.w);
    float sq = v0.x*v0.x + v0.y*v0.y + v0.z*v0.z + v0.w*v0.w
             + v1.x*v1.x + v1.y*v1.y + v1.z*v1.z + v1.w*v1.w;
    s  = warpSum(s);
    sq = warpSum(sq);

    const float mu  = s * (1.0f / D_DIM);
    const float var = sq * (1.0f / D_DIM) - mu * mu;
    const float rs  = rsqrtf(var + 1e-5f);

    const float4 g0 = *(const float4*)(gamma + (lane << 3));
    const float4 g1 = *(const float4*)(gamma + (lane << 3) + 4);
    const float4 b0 = *(const float4*)(beta  + (lane << 3));
    const float4 b1 = *(const float4*)(beta  + (lane << 3) + 4);

    uint4 o;
    o.x = f2h2((v0.x - mu) * rs * g0.x + b0.x, (v0.y - mu) * rs * g0.y + b0.y);
    o.y = f2h2((v0.z - mu) * rs * g0.z + b0.z, (v0.w - mu) * rs * g0.w + b0.w);
    o.z = f2h2((v1.x - mu) * rs * g1.x + b1.x, (v1.y - mu) * rs * g1.y + b1.y);
    o.w = f2h2((v1.z - mu) * rs * g1.z + b1.z, (v1.w - mu) * rs * g1.w + b1.w);
    *(uint4*)(out + row * D_DIM + (lane << 3)) = o;
}

// Softmax over S=512 in-place (fp32) + fp16 copy
__global__ __launch_bounds__(128)
void softmax_kernel(float* __restrict__ p, __half* __restrict__ ph_all)
{
    const long long row = blockIdx.x;
    float* pr = p + row * S_LEN;
    __half* ph = ph_all + row * S_LEN;
    const int t = threadIdx.x;
    const int w = t >> 5, l = t & 31;

    float4 a = *(float4*)(pr + (t << 2));
    __shared__ float sh[4], sh2[4];

    float m = fmaxf(fmaxf(a.x, a.y), fmaxf(a.z, a.w));
    m = warpMax(m);
    if (l == 0) sh[w] = m;
    __syncthreads();
    m = fmaxf(fmaxf(sh[0], sh[1]), fmaxf(sh[2], sh[3]));

    a.x = __expf(a.x - m); a.y = __expf(a.y - m);
    a.z = __expf(a.z - m); a.w = __expf(a.w - m);
    float s = warpSum(a.x + a.y + a.z + a.w);
    if (l == 0) sh2[w] = s;
    __syncthreads();
    const float inv = 1.0f / (sh2[0] + sh2[1] + sh2[2] + sh2[3]);

    a.x *= inv; a.y *= inv; a.z *= inv; a.w *= inv;
    *(float4*)(pr + (t << 2)) = a;
    *(__half2*)(ph + (t << 2))     = __floats2half2_rn(a.x, a.y);
    *(__half2*)(ph + (t << 2) + 2) = __floats2half2_rn(a.z, a.w);
}

// Per-channel mean
__global__ __launch_bounds__(256)
void chmean_kernel(const float* __restrict__ h, float* __restrict__ y)
{
    const int c = blockIdx.x;
    const float4* hc = (const float4*)(h + (long long)c * S_LEN * D_DIM);
    float s = 0.f;
    for (int i = threadIdx.x; i < S_LEN * D_DIM / 4; i += 256) {
        float4 v = hc[i];
        s += (v.x + v.y) + (v.z + v.w);
    }
    __shared__ float sh[8];
    const int w = threadIdx.x >> 5, l = threadIdx.x & 31;
    s = warpSum(s);
    if (l == 0) sh[w] = s;
    __syncthreads();
    if (w == 0) {
        float v = (l < 8) ? sh[l] : 0.f;
        v = warpSum(v);
        if (l == 0) y[c] = v * (1.0f / (S_LEN * D_DIM));
    }
}

// SE gate
__global__ __launch_bounds__(256)
void se_kernel(const float* __restrict__ y,
               const float* __restrict__ W1, const float* __restrict__ b1,
               const float* __restrict__ W2, const float* __restrict__ b2,
               float* __restrict__ gate)
{
    __shared__ float ys[C_CH];
    __shared__ float hid[16];
    const int t = threadIdx.x;
    ys[t] = y[t];
    __syncthreads();
    if (t < 16) {
        float s = b1[t];
        #pragma unroll 8
        for (int c = 0; c < C_CH; c++) s += ys[c] * W1[c * 16 + t];
        hid[t] = fmaxf(s, 0.f);
    }
    __syncthreads();
    float s = b2[t];
    #pragma unroll
    for (int j = 0; j < 16; j++) s += hid[j] * W2[j * C_CH + t];
    gate[t] = 1.0f / (1.0f + __expf(-s));
}

// out = h * gate[c] + x
__global__ __launch_bounds__(256)
void final_kernel(float* __restrict__ out, const float* __restrict__ x,
                  const float* __restrict__ gate)
{
    const long long i4 = (long long)blockIdx.x * 256 + threadIdx.x;
    const int c = (int)(i4 >> 15);
    const float g = gate[c];
    float4 h = ((float4*)out)[i4];
    float4 xv = ((const float4*)x)[i4];
    h.x = h.x * g + xv.x;
    h.y = h.y * g + xv.y;
    h.z = h.z * g + xv.z;
    h.w = h.w * g + xv.w;
    ((float4*)out)[i4] = h;
}

// ---------------------------------------------------------------------------
// Launch
// ---------------------------------------------------------------------------
extern "C" void kernel_launch(void* const* d_in, const int* in_sizes, int n_in,
                              void* d_out, int out_size)
{
    const float* input = (const float*)d_in[0];
    const float* W_emb = (const float*)d_in[1];
    const float* b_emb = (const float*)d_in[2];
    const float* ln_g  = (const float*)d_in[3];
    const float* ln_b  = (const float*)d_in[4];
    const float* W1    = (const float*)d_in[5];
    const float* b1    = (const float*)d_in[6];
    const float* W2    = (const float*)d_in[7];
    const float* b2    = (const float*)d_in[8];
    const float* seW1  = (const float*)d_in[9];
    const float* seb1  = (const float*)d_in[10];
    const float* seW2  = (const float*)d_in[11];
    const float* seb2  = (const float*)d_in[12];

    float* out  = (float*)d_out;               // [C,S,D]
    float* attn = out + ELEMS;                 // [C,S,S] fp32 (output 1)

    float  *px, *py, *pg;
    __half *pih, *pn, *pnT, *po, *pffn, *pah, *pwet, *pw1t, *pw2t;
    cudaGetSymbolAddress((void**)&px,   g_x);
    cudaGetSymbolAddress((void**)&pih,  g_in_h);
    cudaGetSymbolAddress((void**)&pn,   g_n_h);
    cudaGetSymbolAddress((void**)&pnT,  g_nT_h);
    cudaGetSymbolAddress((void**)&po,   g_o_h);
    cudaGetSymbolAddress((void**)&pffn, g_ffn_h);
    cudaGetSymbolAddress((void**)&pah,  g_attn_h);
    cudaGetSymbolAddress((void**)&pwet, g_wembt);
    cudaGetSymbolAddress((void**)&pw1t, g_w1t);
    cudaGetSymbolAddress((void**)&pw2t, g_w2t);
    cudaGetSymbolAddress((void**)&py,   g_y);
    cudaGetSymbolAddress((void**)&pg,   g_gate);

    // raise dynamic smem limit for the GEMM instantiations (idempotent)
    const int DYN = 3 * STAGE_BYTES;   // 61440
    cudaFuncSetAttribute(mma_nt<false, false, false>, cudaFuncAttributeMaxDynamicSharedMemorySize, DYN);
    cudaFuncSetAttribute(mma_nt<true,  false, false>, cudaFuncAttributeMaxDynamicSharedMemorySize, DYN);
    cudaFuncSetAttribute(mma_nt<true,  true,  true >, cudaFuncAttributeMaxDynamicSharedMemorySize, DYN);
    cudaFuncSetAttribute(mma_nt<false, false, true >, cudaFuncAttributeMaxDynamicSharedMemorySize, DYN);

    const dim3 blk(256);
    const long long strideN = (long long)S_LEN * D_DIM;   // 131072
    const long long strideP = (long long)S_LEN * S_LEN;   // 262144

    // 0) weight transposes (fp32 -> fp16, transposed) + input convert
    transpose_f2h<<<dim3(D_DIM / 32, D_IN / 32), blk>>>(W_emb, pwet, D_IN, D_DIM);
    transpose_f2h<<<dim3(D_FF / 32, D_DIM / 32), blk>>>(W1, pw1t, D_DIM, D_FF);
    transpose_f2h<<<dim3(D_DIM / 32, D_FF / 32), blk>>>(W2, pw2t, D_FF, D_DIM);
    f2h_kernel<<<(unsigned)(ELEMS / 2048), blk>>>(input, pih);

    // 1) x = input @ W_emb + b_emb  (NT, B = W_emb^T) -> fp32
    mma_nt<false, false, true><<<dim3(D_DIM / 128, NROWS / 128, 1), blk, DYN>>>(
        pih, pwet, b_emb, px, NROWS, D_DIM, D_IN, 1.0f, 0, 0, 0);

    // 2) n = LayerNorm(x) -> fp16
    ln_kernel<<<NROWS / 8, 256>>>(px, ln_g, ln_b, pn);

    // 3) nT per channel
    transpose_h<<<dim3(D_DIM / 32, S_LEN / 32, C_CH), blk>>>(pn, pnT, S_LEN, D_DIM);

    // 4) scores = (n @ n^T)/16 per channel -> attn fp32
    mma_nt<false, false, false><<<dim3(S_LEN / 128, S_LEN / 128, C_CH), blk, DYN>>>(
        pn, pn, nullptr, attn, S_LEN, S_LEN, D_DIM, 0.0625f,
        strideN, strideN, strideP);

    // 5) softmax in-place + fp16 copy
    softmax_kernel<<<C_CH * S_LEN, 128>>>(attn, pah);

    // 6) o = attn @ n per channel (NT with B = nT) -> fp16
    mma_nt<true, false, false><<<dim3(D_DIM / 128, S_LEN / 128, C_CH), blk, DYN>>>(
        pah, pnT, nullptr, po, S_LEN, D_DIM, S_LEN, 1.0f,
        strideP, strideN, strideN);

    // 7) h1 = relu(o @ W1 + b1) (NT with B = W1T) -> fp16
    mma_nt<true, true, true><<<dim3(D_FF / 128, NROWS / 128, 1), blk, DYN>>>(
        po, pw1t, b1, pffn, NROWS, D_FF, D_DIM, 1.0f, 0, 0, 0);

    // 8) h = h1 @ W2 + b2 (NT with B = W2T) -> fp32 out region
    mma_nt<false, false, true><<<dim3(D_DIM / 128, NROWS / 128, 1), blk, DYN>>>(
        pffn, pw2t, b2, out, NROWS, D_DIM, D_FF, 1.0f, 0, 0, 0);

    // 9) y[c] = mean(h[c])
    chmean_kernel<<<C_CH, 256>>>(out, py);

    // 10) SE gate
    se_kernel<<<1, 256>>>(py, seW1, seb1, seW2, seb2, pg);

    // 11) out = h * g[c] + x
    final_kernel<<<(unsigned)(ELEMS / 1024), 256>>>(out, px, pg);
}